// round 1
// baseline (speedup 1.0000x reference)
#include <cuda_runtime.h>
#include <math.h>

#define N_USER 20000
#define N_ITEM 20000
#define NTOT   40000
#define DD     128
#define HH     4
#define HD     512     // H*D
#define MM     8
#define TT     5
#define E_UI_  40000
#define E_T_   16000

// ---------------- scratch (device globals; no allocation allowed) ----------
__device__ float    g_fc[(size_t)NTOT * HD];      // fc output for current GAT side
__device__ float    g_rst[(size_t)N_USER * HD];   // GAT aggregation / gat output
__device__ float    g_el[NTOT * HH];
__device__ float    g_er[NTOT * HH];
__device__ float    g_e[E_UI_ * HH];
__device__ unsigned g_emax[N_USER * HH];
__device__ float    g_denom[N_USER * HH];
__device__ float    g_trans[(size_t)NTOT * DD];
__device__ float    g_coef[(size_t)TT * E_T_ * MM];
__device__ float    g_ncoef[(size_t)NTOT * MM];
__device__ float    g_s[(size_t)NTOT * DD];
__device__ float    g_cnt[NTOT];
__device__ float    g_node[(size_t)NTOT * DD];
__device__ float    g_feat[(size_t)NTOT * DD];
__device__ float    g_emb1[(size_t)NTOT * DD];
__device__ float    g_emb2[(size_t)NTOT * DD];

// ---------------- helpers ---------------------------------------------------
__device__ __forceinline__ float lrelu(float x) { return x > 0.f ? x : 0.2f * x; }
__device__ __forceinline__ float eluf(float x)  { return x > 0.f ? x : expm1f(x); }
__device__ __forceinline__ unsigned fordu(float f) {
    unsigned u = __float_as_uint(f);
    return (u & 0x80000000u) ? ~u : (u | 0x80000000u);
}
__device__ __forceinline__ float fordinv(unsigned u) {
    return __uint_as_float((u & 0x80000000u) ? (u & 0x7fffffffu) : ~u);
}

__device__ __forceinline__ float blocksum128(float v, float* red) {
#pragma unroll
    for (int o = 16; o; o >>= 1) v += __shfl_down_sync(0xffffffffu, v, o);
    int lane = threadIdx.x & 31, w = threadIdx.x >> 5;
    if (lane == 0) red[w] = v;
    __syncthreads();
    float r = red[0] + red[1] + red[2] + red[3];
    __syncthreads();
    return r;
}

// ---------------- generic tiled SGEMM: C[r,c] = sum_k A'[r,k] * B'[c,k] -----
// A'[r,k] = (coef ? coef[r*8 + k/aSeg] : 1) * A[(gidx?gidx[r]:r)*aSeg + k%aSeg]
// B'[c,k] = B[(k/bSeg)*bStride + c*bSeg + k%bSeg]
// epilogue: scatter-atomicAdd via sidx, or store with optional bias + elu.
__global__ __launch_bounds__(256, 2)
void gemm_kernel(const float* __restrict__ A, const int* __restrict__ gidx,
                 const float* __restrict__ coef,
                 const float* __restrict__ B, int bSeg, long long bStride,
                 float* C, const int* __restrict__ sidx,
                 const float* __restrict__ bias, int act,
                 int Mrows, int K, int aSeg, int ldc)
{
    __shared__ float As[8][128];
    __shared__ float Bs[8][128];
    const int tid  = threadIdx.x;
    const int row0 = blockIdx.y * 128;
    const int col0 = blockIdx.x * 128;
    const int lr   = tid >> 1;
    const int lk   = (tid & 1) * 4;
    const int trow = (tid >> 4) * 8;
    const int tcol = (tid & 15) * 8;

    float acc[8][8];
#pragma unroll
    for (int i = 0; i < 8; i++)
#pragma unroll
        for (int j = 0; j < 8; j++) acc[i][j] = 0.f;

    const int  grow  = row0 + lr;
    const bool rowok = grow < Mrows;
    const int  arow  = rowok ? (gidx ? gidx[grow] : grow) : 0;
    const float* Abase = A + (long long)arow * aSeg;
    const float* Bb    = B + (long long)(col0 + lr) * bSeg + lk;

    for (int kt = 0; kt < K; kt += 8) {
        float4 va = make_float4(0.f, 0.f, 0.f, 0.f);
        if (rowok) {
            va = *(const float4*)(Abase + (kt % aSeg) + lk);
            if (coef) {
                float sc = coef[(long long)grow * MM + (kt / aSeg)];
                va.x *= sc; va.y *= sc; va.z *= sc; va.w *= sc;
            }
        }
        As[lk + 0][lr] = va.x; As[lk + 1][lr] = va.y;
        As[lk + 2][lr] = va.z; As[lk + 3][lr] = va.w;
        float4 vb = *(const float4*)(Bb + (long long)(kt / bSeg) * bStride + (kt % bSeg));
        Bs[lk + 0][lr] = vb.x; Bs[lk + 1][lr] = vb.y;
        Bs[lk + 2][lr] = vb.z; Bs[lk + 3][lr] = vb.w;
        __syncthreads();
#pragma unroll
        for (int k = 0; k < 8; k++) {
            float4 a0 = *(const float4*)&As[k][trow];
            float4 a1 = *(const float4*)&As[k][trow + 4];
            float4 b0 = *(const float4*)&Bs[k][tcol];
            float4 b1 = *(const float4*)&Bs[k][tcol + 4];
            float av[8] = {a0.x, a0.y, a0.z, a0.w, a1.x, a1.y, a1.z, a1.w};
            float bv[8] = {b0.x, b0.y, b0.z, b0.w, b1.x, b1.y, b1.z, b1.w};
#pragma unroll
            for (int i = 0; i < 8; i++)
#pragma unroll
                for (int j = 0; j < 8; j++)
                    acc[i][j] = fmaf(av[i], bv[j], acc[i][j]);
        }
        __syncthreads();
    }

#pragma unroll
    for (int i = 0; i < 8; i++) {
        int r = row0 + trow + i;
        if (r >= Mrows) break;
        if (sidx) {
            long long base = (long long)sidx[r] * ldc + col0 + tcol;
#pragma unroll
            for (int j = 0; j < 8; j++) atomicAdd(&C[base + j], acc[i][j]);
        } else {
            long long base = (long long)r * ldc + col0 + tcol;
#pragma unroll
            for (int j = 0; j < 8; j++) {
                float v = acc[i][j];
                if (bias) v += bias[col0 + tcol + j];
                if (act == 1) v = eluf(v);
                C[base + j] = v;
            }
        }
    }
}

// ---------------- GAT attention scores per node -----------------------------
__global__ void attn_kernel(const float* __restrict__ fc,
                            const float* __restrict__ al, const float* __restrict__ ar,
                            float* __restrict__ el, float* __restrict__ er)
{
    int warp = (blockIdx.x * blockDim.x + threadIdx.x) >> 5;
    int lane = threadIdx.x & 31;
    if (warp >= NTOT) return;
    const float4* row = (const float4*)(fc + (long long)warp * HD);
#pragma unroll
    for (int h = 0; h < HH; h++) {
        float4 v = row[h * 32 + lane];
        float4 a = ((const float4*)al)[h * 32 + lane];
        float4 b = ((const float4*)ar)[h * 32 + lane];
        float s1 = v.x * a.x + v.y * a.y + v.z * a.z + v.w * a.w;
        float s2 = v.x * b.x + v.y * b.y + v.z * b.z + v.w * b.w;
#pragma unroll
        for (int o = 16; o; o >>= 1) {
            s1 += __shfl_down_sync(0xffffffffu, s1, o);
            s2 += __shfl_down_sync(0xffffffffu, s2, o);
        }
        if (lane == 0) { el[warp * HH + h] = s1; er[warp * HH + h] = s2; }
    }
}

// ---------------- GAT edge passes -------------------------------------------
__global__ void edge_p1(const int* __restrict__ srcIdx, const int* __restrict__ dstIdx,
                        int srcOff, int dstOff,
                        const float* __restrict__ el, const float* __restrict__ er,
                        float* __restrict__ eBuf, unsigned* __restrict__ emax)
{
    int i = blockIdx.x * blockDim.x + threadIdx.x;
    if (i >= E_UI_ * HH) return;
    int e = i >> 2, h = i & 3;
    int s = srcIdx[e], dd = dstIdx[e];
    float v = lrelu(el[(s + srcOff) * HH + h] + er[(dd + dstOff) * HH + h]);
    eBuf[i] = v;
    atomicMax(&emax[dd * HH + h], fordu(v));
}

__global__ void edge_p2(const int* __restrict__ srcIdx, const int* __restrict__ dstIdx,
                        int srcOff,
                        const float* __restrict__ fc, const float* __restrict__ eBuf,
                        const unsigned* __restrict__ emax,
                        float* __restrict__ denom, float* __restrict__ rst)
{
    int w = (blockIdx.x * blockDim.x + threadIdx.x) >> 5;
    int lane = threadIdx.x & 31;
    if (w >= E_UI_ * HH) return;
    int e = w >> 2, h = w & 3;
    int s = srcIdx[e], dd = dstIdx[e];
    float ex = expf(eBuf[w] - fordinv(emax[dd * HH + h]));
    if (lane == 0) atomicAdd(&denom[dd * HH + h], ex);
    float4 v = ((const float4*)(fc + (long long)(s + srcOff) * HD + h * DD))[lane];
    float* dst = rst + (long long)dd * HD + h * DD + lane * 4;
    atomicAdd(dst + 0, ex * v.x);
    atomicAdd(dst + 1, ex * v.y);
    atomicAdd(dst + 2, ex * v.z);
    atomicAdd(dst + 3, ex * v.w);
}

__global__ void gat_final(float* __restrict__ rst, const float* __restrict__ denom,
                          const float* __restrict__ bias, int nDst)
{
    long long i = (long long)blockIdx.x * blockDim.x + threadIdx.x;
    if (i >= (long long)nDst * HD) return;
    int c = (int)(i % HD);
    int n = (int)(i / HD);
    int h = c >> 7;
    float den = denom[n * HH + h];
    float v = den > 0.f ? rst[i] / den : 0.f;
    rst[i] = eluf(v + bias[c]);
}

// ---------------- memory layer coefficients ---------------------------------
__global__ void relcoef_kernel(const float* __restrict__ feat, const int* __restrict__ edge_dst,
                               const float* __restrict__ Wc, const float* __restrict__ bc,
                               float* __restrict__ coef)
{
    int warp = (blockIdx.x * blockDim.x + threadIdx.x) >> 5;
    int lane = threadIdx.x & 31;
    if (warp >= TT * E_T_) return;
    int t = warp / E_T_;
    int d = edge_dst[warp];
    float4 hv = ((const float4*)(feat + (long long)d * DD))[lane];
#pragma unroll
    for (int m = 0; m < MM; m++) {
        float4 w = ((const float4*)(Wc + ((long long)t * MM + m) * DD))[lane];
        float s = hv.x * w.x + hv.y * w.y + hv.z * w.z + hv.w * w.w;
#pragma unroll
        for (int o = 16; o; o >>= 1) s += __shfl_down_sync(0xffffffffu, s, o);
        if (lane == 0) coef[(long long)warp * MM + m] = lrelu(s + bc[t * MM + m]);
    }
}

__global__ void ncoef_kernel(const float* __restrict__ feat,
                             const float* __restrict__ Wc, const float* __restrict__ bc,
                             float* __restrict__ coef)
{
    int warp = (blockIdx.x * blockDim.x + threadIdx.x) >> 5;
    int lane = threadIdx.x & 31;
    if (warp >= NTOT) return;
    float4 hv = ((const float4*)(feat + (long long)warp * DD))[lane];
#pragma unroll
    for (int m = 0; m < MM; m++) {
        float4 w = ((const float4*)(Wc + (long long)m * DD))[lane];
        float s = hv.x * w.x + hv.y * w.y + hv.z * w.z + hv.w * w.w;
#pragma unroll
        for (int o = 16; o; o >>= 1) s += __shfl_down_sync(0xffffffffu, s, o);
        if (lane == 0) coef[(long long)warp * MM + m] = lrelu(s + bc[m]);
    }
}

__global__ void cnt_kernel(const int* __restrict__ edge_dst, float* __restrict__ cnt)
{
    int i = blockIdx.x * blockDim.x + threadIdx.x;
    if (i >= TT * E_T_) return;
    atomicAdd(&cnt[edge_dst[i]], 1.f);
}

// ---------------- memory-layer combine (LN + residuals) ---------------------
__global__ void combine_kernel(const float* __restrict__ s, const float* __restrict__ cnt,
                               const float* __restrict__ lnw, const float* __restrict__ lnb,
                               const float* __restrict__ hbias,
                               const float* __restrict__ node, const float* __restrict__ trans,
                               float* __restrict__ featOut, float* __restrict__ embOut)
{
    __shared__ float red[4];
    int n = blockIdx.x, d = threadIdx.x;
    float c = fmaxf(cnt[n], 1.f);
    float agg = s[(long long)n * DD + d] / c;
    float mean = blocksum128(agg, red) * (1.f / DD);
    float df = agg - mean;
    float var = blocksum128(df * df, red) * (1.f / DD);
    float rep = df * rsqrtf(var + 1e-5f) * lnw[d] + lnb[d] + hbias[d]
              + node[(long long)n * DD + d];
    float f = lrelu(rep) + trans[(long long)n * DD + d];
    featOut[(long long)n * DD + d] = f;
    embOut[(long long)n * DD + d]  = f;
}

// ---------------- final layernorm over concat(emb0, e1, e2) -----------------
__global__ void final_kernel(const float* __restrict__ emb0,
                             const float* __restrict__ e1, const float* __restrict__ e2,
                             const float* __restrict__ w, const float* __restrict__ b,
                             float* __restrict__ out)
{
    __shared__ float red[4];
    int n = blockIdx.x, d = threadIdx.x;
    float x0 = emb0[(long long)n * DD + d];
    float x1 = e1[(long long)n * DD + d];
    float x2 = e2[(long long)n * DD + d];
    float mean = blocksum128(x0 + x1 + x2, red) * (1.f / 384.f);
    float d0 = x0 - mean, d1 = x1 - mean, d2 = x2 - mean;
    float var = blocksum128(d0 * d0 + d1 * d1 + d2 * d2, red) * (1.f / 384.f);
    float rs = rsqrtf(var + 1e-5f);
    long long base = (long long)n * 384;
    out[base + d]       = d0 * rs * w[d]       + b[d];
    out[base + 128 + d] = d1 * rs * w[128 + d] + b[128 + d];
    out[base + 256 + d] = d2 * rs * w[256 + d] + b[256 + d];
}

// ---------------- host driver ------------------------------------------------
extern "C" void kernel_launch(void* const* d_in, const int* in_sizes, int n_in,
                              void* d_out, int out_size)
{
    const float* embedding = (const float*)d_in[0];
    const float* gat_fc_W  = (const float*)d_in[1];
    const float* gat_al    = (const float*)d_in[2];
    const float* gat_ar    = (const float*)d_in[3];
    const float* gat_bias  = (const float*)d_in[4];
    const float* proj_W    = (const float*)d_in[5];
    const float* proj_b    = (const float*)d_in[6];
    const float* rel_Wc    = (const float*)d_in[7];
    const float* rel_bc    = (const float*)d_in[8];
    const float* rel_Ww    = (const float*)d_in[9];
    const float* node_Wc   = (const float*)d_in[10];
    const float* node_bc   = (const float*)d_in[11];
    const float* node_Ww   = (const float*)d_in[12];
    const float* h_bias    = (const float*)d_in[13];
    const float* ln_w      = (const float*)d_in[14];
    const float* ln_b      = (const float*)d_in[15];
    const float* fln_w     = (const float*)d_in[16];
    const float* fln_b     = (const float*)d_in[17];
    const int*   src_u     = (const int*)d_in[18];
    const int*   dst_i     = (const int*)d_in[19];
    const int*   edge_src  = (const int*)d_in[20];
    const int*   edge_dst  = (const int*)d_in[21];
    float* out = (float*)d_out;

    float *p_fc, *p_rst, *p_el, *p_er, *p_e, *p_denom, *p_trans, *p_coef,
          *p_ncoef, *p_s, *p_cnt, *p_node, *p_feat, *p_e1, *p_e2;
    unsigned* p_emax;
    cudaGetSymbolAddress((void**)&p_fc, g_fc);
    cudaGetSymbolAddress((void**)&p_rst, g_rst);
    cudaGetSymbolAddress((void**)&p_el, g_el);
    cudaGetSymbolAddress((void**)&p_er, g_er);
    cudaGetSymbolAddress((void**)&p_e, g_e);
    cudaGetSymbolAddress((void**)&p_emax, g_emax);
    cudaGetSymbolAddress((void**)&p_denom, g_denom);
    cudaGetSymbolAddress((void**)&p_trans, g_trans);
    cudaGetSymbolAddress((void**)&p_coef, g_coef);
    cudaGetSymbolAddress((void**)&p_ncoef, g_ncoef);
    cudaGetSymbolAddress((void**)&p_s, g_s);
    cudaGetSymbolAddress((void**)&p_cnt, g_cnt);
    cudaGetSymbolAddress((void**)&p_node, g_node);
    cudaGetSymbolAddress((void**)&p_feat, g_feat);
    cudaGetSymbolAddress((void**)&p_e1, g_emb1);
    cudaGetSymbolAddress((void**)&p_e2, g_emb2);

    auto gemm = [&](const float* A, const int* gidx, const float* coefp,
                    const float* B, int bSeg, long long bStride,
                    float* C, const int* sidx, const float* bias, int act,
                    int M, int Nc, int K, int aSeg, int ldc) {
        dim3 g(Nc / 128, (M + 127) / 128);
        gemm_kernel<<<g, 256>>>(A, gidx, coefp, B, bSeg, bStride,
                                C, sidx, bias, act, M, K, aSeg, ldc);
    };

    cudaMemcpyAsync(p_feat, embedding, (size_t)NTOT * DD * 4, cudaMemcpyDeviceToDevice);
    cudaMemsetAsync(p_cnt, 0, NTOT * 4);
    cnt_kernel<<<(TT * E_T_ + 255) / 256, 256>>>(edge_dst, p_cnt);

    for (int l = 0; l < 2; l++) {
        for (int side = 0; side < 2; side++) {
            int g = l * 2 + side;
            // shared fc over all nodes
            gemm(p_feat, nullptr, nullptr, gat_fc_W + (size_t)g * HD * DD, DD, 0,
                 p_fc, nullptr, nullptr, 0, NTOT, HD, DD, DD, HD);
            attn_kernel<<<(NTOT * 32 + 255) / 256, 256>>>(
                p_fc, gat_al + (size_t)g * HH * DD, gat_ar + (size_t)g * HH * DD, p_el, p_er);
            cudaMemsetAsync(p_emax, 0, N_USER * HH * 4);
            cudaMemsetAsync(p_denom, 0, N_USER * HH * 4);
            cudaMemsetAsync(p_rst, 0, (size_t)N_USER * HD * 4);
            const int* sIdx = side == 0 ? dst_i : src_u;
            const int* dIdx = side == 0 ? src_u : dst_i;
            int sOff = side == 0 ? N_USER : 0;
            int dOff = side == 0 ? 0 : N_USER;
            edge_p1<<<(E_UI_ * HH + 255) / 256, 256>>>(sIdx, dIdx, sOff, dOff,
                                                       p_el, p_er, p_e, p_emax);
            edge_p2<<<(E_UI_ * HH * 32 + 255) / 256, 256>>>(sIdx, dIdx, sOff,
                                                            p_fc, p_e, p_emax, p_denom, p_rst);
            gat_final<<<((size_t)N_USER * HD + 255) / 256, 256>>>(
                p_rst, p_denom, gat_bias + (size_t)g * HD, N_USER);
            gemm(p_rst, nullptr, nullptr, proj_W + (size_t)g * DD * HD, HD, 0,
                 p_trans + (size_t)side * N_USER * DD, nullptr,
                 proj_b + (size_t)g * DD, 1, N_USER, DD, HD, HD, DD);
        }
        // memory layer
        relcoef_kernel<<<(TT * E_T_ * 32 + 255) / 256, 256>>>(
            p_feat, edge_dst, rel_Wc + (size_t)l * TT * MM * DD,
            rel_bc + (size_t)l * TT * MM, p_coef);
        ncoef_kernel<<<(NTOT * 32 + 255) / 256, 256>>>(
            p_feat, node_Wc + (size_t)l * MM * DD, node_bc + (size_t)l * MM, p_ncoef);
        cudaMemsetAsync(p_s, 0, (size_t)NTOT * DD * 4);
        for (int t = 0; t < TT; t++) {
            gemm(p_feat, edge_src + t * E_T_, p_coef + (size_t)t * E_T_ * MM,
                 rel_Ww + ((size_t)(l * TT + t)) * MM * DD * DD, DD, (long long)DD * DD,
                 p_s, edge_dst + t * E_T_, nullptr, 0,
                 E_T_, DD, MM * DD, DD, DD);
        }
        gemm(p_feat, nullptr, p_ncoef, node_Ww + (size_t)l * MM * DD * DD, DD,
             (long long)DD * DD, p_node, nullptr, nullptr, 0,
             NTOT, DD, MM * DD, DD, DD);
        combine_kernel<<<NTOT, DD>>>(p_s, p_cnt, ln_w + (size_t)l * DD, ln_b + (size_t)l * DD,
                                     h_bias + (size_t)l * DD, p_node, p_trans,
                                     p_feat, l == 0 ? p_e1 : p_e2);
    }
    final_kernel<<<NTOT, DD>>>(embedding, p_e1, p_e2, fln_w, fln_b, out);
    (void)in_sizes; (void)n_in; (void)out_size;
}

// round 3
// speedup vs baseline: 2.5650x; 2.5650x over previous
#include <cuda_runtime.h>
#include <math.h>

#define N_USER 20000
#define N_ITEM 20000
#define NTOT   40000
#define DD     128
#define HH     4
#define HD     512     // H*D
#define MM     8
#define TT     5
#define E_UI_  40000
#define E_T_   16000

// ---------------- scratch (device globals; no allocation allowed) ----------
__device__ float    g_fc[(size_t)NTOT * HD];
__device__ float    g_rst[(size_t)N_USER * HD];
__device__ float    g_el[NTOT * HH];
__device__ float    g_er[NTOT * HH];
__device__ float    g_e[E_UI_ * HH];
__device__ unsigned g_emax[N_USER * HH];
__device__ float    g_denom[N_USER * HH];
__device__ float    g_trans[(size_t)NTOT * DD];
__device__ float    g_coef[(size_t)TT * E_T_ * MM];
__device__ float    g_ncoef[(size_t)NTOT * MM];
__device__ float    g_s[(size_t)NTOT * DD];
__device__ float    g_cnt[NTOT];
__device__ float    g_node[(size_t)NTOT * DD];
__device__ float    g_feat[(size_t)NTOT * DD];
__device__ float    g_emb1[(size_t)NTOT * DD];
__device__ float    g_emb2[(size_t)NTOT * DD];
// tf32-pre-rounded weights
__device__ float    g_wfc[2 * 2 * HD * DD];
__device__ float    g_wproj[2 * 2 * DD * HD];
__device__ float    g_wrel[2 * TT * MM * DD * DD];
__device__ float    g_wnode[2 * MM * DD * DD];

// ---------------- helpers ---------------------------------------------------
__device__ __forceinline__ float lrelu(float x) { return x > 0.f ? x : 0.2f * x; }
__device__ __forceinline__ float eluf(float x)  { return x > 0.f ? x : expm1f(x); }
__device__ __forceinline__ unsigned fordu(float f) {
    unsigned u = __float_as_uint(f);
    return (u & 0x80000000u) ? ~u : (u | 0x80000000u);
}
__device__ __forceinline__ float fordinv(unsigned u) {
    return __uint_as_float((u & 0x80000000u) ? (u & 0x7fffffffu) : ~u);
}
__device__ __forceinline__ unsigned f2tf32(float x) {
    unsigned r; asm("cvt.rna.tf32.f32 %0, %1;" : "=r"(r) : "f"(x)); return r;
}
__device__ __forceinline__ void mma1688(float* c, const unsigned* a, const unsigned* b) {
    asm volatile("mma.sync.aligned.m16n8k8.row.col.f32.tf32.tf32.f32 "
                 "{%0,%1,%2,%3},{%4,%5,%6,%7},{%8,%9},{%0,%1,%2,%3};"
                 : "+f"(c[0]), "+f"(c[1]), "+f"(c[2]), "+f"(c[3])
                 : "r"(a[0]), "r"(a[1]), "r"(a[2]), "r"(a[3]), "r"(b[0]), "r"(b[1]));
}

__device__ __forceinline__ float blocksum128(float v, float* red) {
#pragma unroll
    for (int o = 16; o; o >>= 1) v += __shfl_down_sync(0xffffffffu, v, o);
    int lane = threadIdx.x & 31, w = threadIdx.x >> 5;
    if (lane == 0) red[w] = v;
    __syncthreads();
    float r = red[0] + red[1] + red[2] + red[3];
    __syncthreads();
    return r;
}

// ---------------- weight pre-round to tf32 ----------------------------------
__global__ void round_tf32(const float* __restrict__ in, float* __restrict__ out, int n)
{
    int i = blockIdx.x * blockDim.x + threadIdx.x;
    if (i < n) out[i] = __uint_as_float(f2tf32(in[i]));
}

// ---------------- tf32 tensor-core GEMM -------------------------------------
// C[r,c] = sum_k A'[r,k] * B'[c,k]
// A'[r,k] = (coef ? coef[(t*Mrows+r)*8 + k/aSeg] : 1) * A[(gidx?gidx[t*Mrows+r]:r)*aSeg + k%aSeg]
// B'[c,k] = B[t*bTStride + (k/bSeg)*bStride + c*bSeg + k%bSeg]   (pre-rounded to tf32)
// epilogue: scatter-atomicAdd via sidx[t*Mrows+r], or store with bias+elu.
#define BK 32
#define SMF 19456
#define SMB (SMF * 4)

__global__ __launch_bounds__(256, 2)
void gemm_tf32(const float* __restrict__ A, const int* __restrict__ gidx,
               const float* __restrict__ coef,
               const float* __restrict__ B, int bSeg, long long bStride, long long bTStride,
               float* __restrict__ C, const int* __restrict__ sidx,
               const float* __restrict__ bias, int act,
               int Mrows, int K, int aSeg, int ldc, int tilesPerT)
{
    extern __shared__ float sm[];
    float* sCoef = sm + 18432;

    const int tid  = threadIdx.x;
    const int lane = tid & 31, wid = tid >> 5;
    const int warpM = wid & 3, warpN = wid >> 2;   // 4 x 2 warps; warp tile 32x64
    const int t    = blockIdx.y / tilesPerT;
    const int row0 = (blockIdx.y % tilesPerT) * 128;
    const int col0 = blockIdx.x * 128;

    const int lrow = tid >> 1;
    const int lcol = (tid & 1) * 16;
    const int growL  = row0 + lrow;
    const bool rowokL = growL < Mrows;
    const int arowL  = rowokL ? (gidx ? gidx[(long long)t * Mrows + growL] : growL) : 0;
    const float* AbaseL = A + (long long)arowL * aSeg + lcol;
    const float* BbaseL = B + t * bTStride + (long long)(col0 + lrow) * bSeg + lcol;
    const int aBytes = rowokL ? 16 : 0;

    if (coef) {
        for (int i = tid; i < 1024; i += 256) {
            int r = i >> 3, m = i & 7;
            int gr = row0 + r;
            sCoef[i] = (gr < Mrows) ? coef[((long long)t * Mrows + gr) * 8 + m] : 0.f;
        }
    }

    float acc[2][8][4];
#pragma unroll
    for (int i = 0; i < 2; i++)
#pragma unroll
        for (int j = 0; j < 8; j++)
#pragma unroll
            for (int q = 0; q < 4; q++) acc[i][j][q] = 0.f;

    const int ntiles = K / BK;

    auto loadTile = [&](int kt, int b) {
        const float* ga = AbaseL + (kt * BK) % aSeg;
        const float* gb = BbaseL + (long long)((kt * BK) / bSeg) * bStride + (kt * BK) % bSeg;
        unsigned da = (unsigned)__cvta_generic_to_shared(&sm[b * 9216 + lrow * 36 + lcol]);
        unsigned db = (unsigned)__cvta_generic_to_shared(&sm[b * 9216 + 4608 + lrow * 36 + lcol]);
#pragma unroll
        for (int j = 0; j < 4; j++) {
            asm volatile("cp.async.ca.shared.global [%0], [%1], 16, %2;"
                         :: "r"(da + j * 16), "l"(ga + j * 4), "r"(aBytes));
            asm volatile("cp.async.ca.shared.global [%0], [%1], 16;"
                         :: "r"(db + j * 16), "l"(gb + j * 4));
        }
    };

    loadTile(0, 0);
    asm volatile("cp.async.commit_group;");
    int buf = 0;
    for (int kt = 0; kt < ntiles; kt++) {
        if (kt + 1 < ntiles) {
            loadTile(kt + 1, buf ^ 1);
            asm volatile("cp.async.commit_group;");
            asm volatile("cp.async.wait_group 1;");
        } else {
            asm volatile("cp.async.wait_group 0;");
        }
        __syncthreads();

        const float* pA = sm + buf * 9216;
        const float* pB = pA + 4608;
        float cf[2][2];
        if (coef) {
            int seg = (kt * BK) / aSeg;
#pragma unroll
            for (int mt = 0; mt < 2; mt++) {
                int rr = warpM * 32 + mt * 16 + (lane >> 2);
                cf[mt][0] = sCoef[rr * 8 + seg];
                cf[mt][1] = sCoef[(rr + 8) * 8 + seg];
            }
        }
#pragma unroll
        for (int kk = 0; kk < BK; kk += 8) {
            unsigned af[2][4], bf[8][2];
#pragma unroll
            for (int mt = 0; mt < 2; mt++) {
                int rr = warpM * 32 + mt * 16 + (lane >> 2);
                int kc = kk + (lane & 3);
                float x0 = pA[rr * 36 + kc];
                float x1 = pA[(rr + 8) * 36 + kc];
                float x2 = pA[rr * 36 + kc + 4];
                float x3 = pA[(rr + 8) * 36 + kc + 4];
                if (coef) {
                    x0 *= cf[mt][0]; x1 *= cf[mt][1];
                    x2 *= cf[mt][0]; x3 *= cf[mt][1];
                }
                af[mt][0] = f2tf32(x0); af[mt][1] = f2tf32(x1);
                af[mt][2] = f2tf32(x2); af[mt][3] = f2tf32(x3);
            }
#pragma unroll
            for (int nt = 0; nt < 8; nt++) {
                int nn = warpN * 64 + nt * 8 + (lane >> 2);
                int kc = kk + (lane & 3);
                bf[nt][0] = __float_as_uint(pB[nn * 36 + kc]);
                bf[nt][1] = __float_as_uint(pB[nn * 36 + kc + 4]);
            }
#pragma unroll
            for (int mt = 0; mt < 2; mt++)
#pragma unroll
                for (int nt = 0; nt < 8; nt++)
                    mma1688(acc[mt][nt], af[mt], bf[nt]);
        }
        __syncthreads();
        buf ^= 1;
    }

    // epilogue  (FIX: column includes warpN*64, matching B fragment columns)
#pragma unroll
    for (int mt = 0; mt < 2; mt++)
#pragma unroll
        for (int h = 0; h < 2; h++) {
            int r = row0 + warpM * 32 + mt * 16 + (lane >> 2) + 8 * h;
            if (r >= Mrows) continue;
            if (sidx) {
                long long orow = sidx[(long long)t * Mrows + r];
                long long base = orow * ldc + col0;
#pragma unroll
                for (int nt = 0; nt < 8; nt++) {
                    int c = warpN * 64 + nt * 8 + 2 * (lane & 3);
                    atomicAdd(&C[base + c],     acc[mt][nt][2 * h]);
                    atomicAdd(&C[base + c + 1], acc[mt][nt][2 * h + 1]);
                }
            } else {
                long long base = (long long)r * ldc + col0;
#pragma unroll
                for (int nt = 0; nt < 8; nt++) {
                    int c = warpN * 64 + nt * 8 + 2 * (lane & 3);
                    float v0 = acc[mt][nt][2 * h];
                    float v1 = acc[mt][nt][2 * h + 1];
                    if (bias) { v0 += bias[col0 + c]; v1 += bias[col0 + c + 1]; }
                    if (act == 1) { v0 = eluf(v0); v1 = eluf(v1); }
                    float2 v = make_float2(v0, v1);
                    *(float2*)&C[base + c] = v;
                }
            }
        }
}

// ---------------- GAT attention scores per node -----------------------------
__global__ void attn_kernel(const float* __restrict__ fc,
                            const float* __restrict__ al, const float* __restrict__ ar,
                            float* __restrict__ el, float* __restrict__ er)
{
    int warp = (blockIdx.x * blockDim.x + threadIdx.x) >> 5;
    int lane = threadIdx.x & 31;
    if (warp >= NTOT) return;
    const float4* row = (const float4*)(fc + (long long)warp * HD);
#pragma unroll
    for (int h = 0; h < HH; h++) {
        float4 v = row[h * 32 + lane];
        float4 a = ((const float4*)al)[h * 32 + lane];
        float4 b = ((const float4*)ar)[h * 32 + lane];
        float s1 = v.x * a.x + v.y * a.y + v.z * a.z + v.w * a.w;
        float s2 = v.x * b.x + v.y * b.y + v.z * b.z + v.w * b.w;
#pragma unroll
        for (int o = 16; o; o >>= 1) {
            s1 += __shfl_down_sync(0xffffffffu, s1, o);
            s2 += __shfl_down_sync(0xffffffffu, s2, o);
        }
        if (lane == 0) { el[warp * HH + h] = s1; er[warp * HH + h] = s2; }
    }
}

// ---------------- GAT edge passes -------------------------------------------
__global__ void edge_p1(const int* __restrict__ srcIdx, const int* __restrict__ dstIdx,
                        int srcOff, int dstOff,
                        const float* __restrict__ el, const float* __restrict__ er,
                        float* __restrict__ eBuf, unsigned* __restrict__ emax)
{
    int i = blockIdx.x * blockDim.x + threadIdx.x;
    if (i >= E_UI_ * HH) return;
    int e = i >> 2, h = i & 3;
    int s = srcIdx[e], dd = dstIdx[e];
    float v = lrelu(el[(s + srcOff) * HH + h] + er[(dd + dstOff) * HH + h]);
    eBuf[i] = v;
    atomicMax(&emax[dd * HH + h], fordu(v));
}

__global__ void edge_p2(const int* __restrict__ srcIdx, const int* __restrict__ dstIdx,
                        int srcOff,
                        const float* __restrict__ fc, const float* __restrict__ eBuf,
                        const unsigned* __restrict__ emax,
                        float* __restrict__ denom, float* __restrict__ rst)
{
    int w = (blockIdx.x * blockDim.x + threadIdx.x) >> 5;
    int lane = threadIdx.x & 31;
    if (w >= E_UI_ * HH) return;
    int e = w >> 2, h = w & 3;
    int s = srcIdx[e], dd = dstIdx[e];
    float ex = expf(eBuf[w] - fordinv(emax[dd * HH + h]));
    if (lane == 0) atomicAdd(&denom[dd * HH + h], ex);
    float4 v = ((const float4*)(fc + (long long)(s + srcOff) * HD + h * DD))[lane];
    float* dst = rst + (long long)dd * HD + h * DD + lane * 4;
    atomicAdd(dst + 0, ex * v.x);
    atomicAdd(dst + 1, ex * v.y);
    atomicAdd(dst + 2, ex * v.z);
    atomicAdd(dst + 3, ex * v.w);
}

__global__ void gat_final(float* __restrict__ rst, const float* __restrict__ denom,
                          const float* __restrict__ bias, int nDst)
{
    long long i = (long long)blockIdx.x * blockDim.x + threadIdx.x;
    if (i >= (long long)nDst * HD) return;
    int c = (int)(i % HD);
    int n = (int)(i / HD);
    int h = c >> 7;
    float den = denom[n * HH + h];
    float v = den > 0.f ? rst[i] / den : 0.f;
    rst[i] = eluf(v + bias[c]);
}

// ---------------- memory layer coefficients ---------------------------------
__global__ void relcoef_kernel(const float* __restrict__ feat, const int* __restrict__ edge_dst,
                               const float* __restrict__ Wc, const float* __restrict__ bc,
                               float* __restrict__ coef)
{
    int warp = (blockIdx.x * blockDim.x + threadIdx.x) >> 5;
    int lane = threadIdx.x & 31;
    if (warp >= TT * E_T_) return;
    int t = warp / E_T_;
    int d = edge_dst[warp];
    float4 hv = ((const float4*)(feat + (long long)d * DD))[lane];
#pragma unroll
    for (int m = 0; m < MM; m++) {
        float4 w = ((const float4*)(Wc + ((long long)t * MM + m) * DD))[lane];
        float s = hv.x * w.x + hv.y * w.y + hv.z * w.z + hv.w * w.w;
#pragma unroll
        for (int o = 16; o; o >>= 1) s += __shfl_down_sync(0xffffffffu, s, o);
        if (lane == 0) coef[(long long)warp * MM + m] = lrelu(s + bc[t * MM + m]);
    }
}

__global__ void ncoef_kernel(const float* __restrict__ feat,
                             const float* __restrict__ Wc, const float* __restrict__ bc,
                             float* __restrict__ coef)
{
    int warp = (blockIdx.x * blockDim.x + threadIdx.x) >> 5;
    int lane = threadIdx.x & 31;
    if (warp >= NTOT) return;
    float4 hv = ((const float4*)(feat + (long long)warp * DD))[lane];
#pragma unroll
    for (int m = 0; m < MM; m++) {
        float4 w = ((const float4*)(Wc + (long long)m * DD))[lane];
        float s = hv.x * w.x + hv.y * w.y + hv.z * w.z + hv.w * w.w;
#pragma unroll
        for (int o = 16; o; o >>= 1) s += __shfl_down_sync(0xffffffffu, s, o);
        if (lane == 0) coef[(long long)warp * MM + m] = lrelu(s + bc[m]);
    }
}

__global__ void cnt_kernel(const int* __restrict__ edge_dst, float* __restrict__ cnt)
{
    int i = blockIdx.x * blockDim.x + threadIdx.x;
    if (i >= TT * E_T_) return;
    atomicAdd(&cnt[edge_dst[i]], 1.f);
}

// ---------------- memory-layer combine (LN + residuals) ---------------------
__global__ void combine_kernel(const float* __restrict__ s, const float* __restrict__ cnt,
                               const float* __restrict__ lnw, const float* __restrict__ lnb,
                               const float* __restrict__ hbias,
                               const float* __restrict__ node, const float* __restrict__ trans,
                               float* __restrict__ featOut, float* __restrict__ embOut)
{
    __shared__ float red[4];
    int n = blockIdx.x, d = threadIdx.x;
    float c = fmaxf(cnt[n], 1.f);
    float agg = s[(long long)n * DD + d] / c;
    float mean = blocksum128(agg, red) * (1.f / DD);
    float df = agg - mean;
    float var = blocksum128(df * df, red) * (1.f / DD);
    float rep = df * rsqrtf(var + 1e-5f) * lnw[d] + lnb[d] + hbias[d]
              + node[(long long)n * DD + d];
    float f = lrelu(rep) + trans[(long long)n * DD + d];
    featOut[(long long)n * DD + d] = f;
    embOut[(long long)n * DD + d]  = f;
}

// ---------------- final layernorm over concat(emb0, e1, e2) -----------------
__global__ void final_kernel(const float* __restrict__ emb0,
                             const float* __restrict__ e1, const float* __restrict__ e2,
                             const float* __restrict__ w, const float* __restrict__ b,
                             float* __restrict__ out)
{
    __shared__ float red[4];
    int n = blockIdx.x, d = threadIdx.x;
    float x0 = emb0[(long long)n * DD + d];
    float x1 = e1[(long long)n * DD + d];
    float x2 = e2[(long long)n * DD + d];
    float mean = blocksum128(x0 + x1 + x2, red) * (1.f / 384.f);
    float d0 = x0 - mean, d1 = x1 - mean, d2 = x2 - mean;
    float var = blocksum128(d0 * d0 + d1 * d1 + d2 * d2, red) * (1.f / 384.f);
    float rs = rsqrtf(var + 1e-5f);
    long long base = (long long)n * 384;
    out[base + d]       = d0 * rs * w[d]       + b[d];
    out[base + 128 + d] = d1 * rs * w[128 + d] + b[128 + d];
    out[base + 256 + d] = d2 * rs * w[256 + d] + b[256 + d];
}

// ---------------- host driver ------------------------------------------------
extern "C" void kernel_launch(void* const* d_in, const int* in_sizes, int n_in,
                              void* d_out, int out_size)
{
    const float* embedding = (const float*)d_in[0];
    const float* gat_fc_W  = (const float*)d_in[1];
    const float* gat_al    = (const float*)d_in[2];
    const float* gat_ar    = (const float*)d_in[3];
    const float* gat_bias  = (const float*)d_in[4];
    const float* proj_W    = (const float*)d_in[5];
    const float* proj_b    = (const float*)d_in[6];
    const float* rel_Wc    = (const float*)d_in[7];
    const float* rel_bc    = (const float*)d_in[8];
    const float* rel_Ww    = (const float*)d_in[9];
    const float* node_Wc   = (const float*)d_in[10];
    const float* node_bc   = (const float*)d_in[11];
    const float* node_Ww   = (const float*)d_in[12];
    const float* h_bias    = (const float*)d_in[13];
    const float* ln_w      = (const float*)d_in[14];
    const float* ln_b      = (const float*)d_in[15];
    const float* fln_w     = (const float*)d_in[16];
    const float* fln_b     = (const float*)d_in[17];
    const int*   src_u     = (const int*)d_in[18];
    const int*   dst_i     = (const int*)d_in[19];
    const int*   edge_src  = (const int*)d_in[20];
    const int*   edge_dst  = (const int*)d_in[21];
    float* out = (float*)d_out;

    float *p_fc, *p_rst, *p_el, *p_er, *p_e, *p_denom, *p_trans, *p_coef,
          *p_ncoef, *p_s, *p_cnt, *p_node, *p_feat, *p_e1, *p_e2,
          *p_wfc, *p_wproj, *p_wrel, *p_wnode;
    unsigned* p_emax;
    cudaGetSymbolAddress((void**)&p_fc, g_fc);
    cudaGetSymbolAddress((void**)&p_rst, g_rst);
    cudaGetSymbolAddress((void**)&p_el, g_el);
    cudaGetSymbolAddress((void**)&p_er, g_er);
    cudaGetSymbolAddress((void**)&p_e, g_e);
    cudaGetSymbolAddress((void**)&p_emax, g_emax);
    cudaGetSymbolAddress((void**)&p_denom, g_denom);
    cudaGetSymbolAddress((void**)&p_trans, g_trans);
    cudaGetSymbolAddress((void**)&p_coef, g_coef);
    cudaGetSymbolAddress((void**)&p_ncoef, g_ncoef);
    cudaGetSymbolAddress((void**)&p_s, g_s);
    cudaGetSymbolAddress((void**)&p_cnt, g_cnt);
    cudaGetSymbolAddress((void**)&p_node, g_node);
    cudaGetSymbolAddress((void**)&p_feat, g_feat);
    cudaGetSymbolAddress((void**)&p_e1, g_emb1);
    cudaGetSymbolAddress((void**)&p_e2, g_emb2);
    cudaGetSymbolAddress((void**)&p_wfc, g_wfc);
    cudaGetSymbolAddress((void**)&p_wproj, g_wproj);
    cudaGetSymbolAddress((void**)&p_wrel, g_wrel);
    cudaGetSymbolAddress((void**)&p_wnode, g_wnode);

    cudaFuncSetAttribute(gemm_tf32, cudaFuncAttributeMaxDynamicSharedMemorySize, SMB);

    auto gemmT = [&](const float* A, const int* gidx, const float* coefp,
                     const float* B, int bSeg, long long bStride, long long bTStride,
                     float* C, const int* sidx, const float* bias, int act,
                     int M, int Nc, int K, int aSeg, int ldc, int tCount) {
        int tiles = (M + 127) / 128;
        dim3 g(Nc / 128, tiles * tCount);
        gemm_tf32<<<g, 256, SMB>>>(A, gidx, coefp, B, bSeg, bStride, bTStride,
                                   C, sidx, bias, act, M, K, aSeg, ldc, tiles);
    };

    // pre-round weights to tf32 (once per launch)
    round_tf32<<<(2*2*HD*DD + 255) / 256, 256>>>(gat_fc_W, p_wfc, 2*2*HD*DD);
    round_tf32<<<(2*2*DD*HD + 255) / 256, 256>>>(proj_W, p_wproj, 2*2*DD*HD);
    round_tf32<<<(2*TT*MM*DD*DD + 255) / 256, 256>>>(rel_Ww, p_wrel, 2*TT*MM*DD*DD);
    round_tf32<<<(2*MM*DD*DD + 255) / 256, 256>>>(node_Ww, p_wnode, 2*MM*DD*DD);

    cudaMemcpyAsync(p_feat, embedding, (size_t)NTOT * DD * 4, cudaMemcpyDeviceToDevice);
    cudaMemsetAsync(p_cnt, 0, NTOT * 4);
    cnt_kernel<<<(TT * E_T_ + 255) / 256, 256>>>(edge_dst, p_cnt);

    for (int l = 0; l < 2; l++) {
        for (int side = 0; side < 2; side++) {
            int g = l * 2 + side;
            gemmT(p_feat, nullptr, nullptr, p_wfc + (size_t)g * HD * DD, DD, 0, 0,
                  p_fc, nullptr, nullptr, 0, NTOT, HD, DD, DD, HD, 1);
            attn_kernel<<<(NTOT * 32 + 255) / 256, 256>>>(
                p_fc, gat_al + (size_t)g * HH * DD, gat_ar + (size_t)g * HH * DD, p_el, p_er);
            cudaMemsetAsync(p_emax, 0, N_USER * HH * 4);
            cudaMemsetAsync(p_denom, 0, N_USER * HH * 4);
            cudaMemsetAsync(p_rst, 0, (size_t)N_USER * HD * 4);
            const int* sIdx = side == 0 ? dst_i : src_u;
            const int* dIdx = side == 0 ? src_u : dst_i;
            int sOff = side == 0 ? N_USER : 0;
            int dOff = side == 0 ? 0 : N_USER;
            edge_p1<<<(E_UI_ * HH + 255) / 256, 256>>>(sIdx, dIdx, sOff, dOff,
                                                       p_el, p_er, p_e, p_emax);
            edge_p2<<<(E_UI_ * HH * 32 + 255) / 256, 256>>>(sIdx, dIdx, sOff,
                                                            p_fc, p_e, p_emax, p_denom, p_rst);
            gat_final<<<((size_t)N_USER * HD + 255) / 256, 256>>>(
                p_rst, p_denom, gat_bias + (size_t)g * HD, N_USER);
            gemmT(p_rst, nullptr, nullptr, p_wproj + (size_t)g * DD * HD, HD, 0, 0,
                  p_trans + (size_t)side * N_USER * DD, nullptr,
                  proj_b + (size_t)g * DD, 1, N_USER, DD, HD, HD, DD, 1);
        }
        // memory layer
        relcoef_kernel<<<(TT * E_T_ * 32 + 255) / 256, 256>>>(
            p_feat, edge_dst, rel_Wc + (size_t)l * TT * MM * DD,
            rel_bc + (size_t)l * TT * MM, p_coef);
        ncoef_kernel<<<(NTOT * 32 + 255) / 256, 256>>>(
            p_feat, node_Wc + (size_t)l * MM * DD, node_bc + (size_t)l * MM, p_ncoef);
        cudaMemsetAsync(p_s, 0, (size_t)NTOT * DD * 4);
        // all 5 relation GEMMs fused into one launch (t = blockIdx.y / 125)
        gemmT(p_feat, edge_src, p_coef,
              p_wrel + (size_t)l * TT * MM * DD * DD, DD, (long long)DD * DD,
              (long long)MM * DD * DD,
              p_s, edge_dst, nullptr, 0,
              E_T_, DD, MM * DD, DD, DD, TT);
        gemmT(p_feat, nullptr, p_ncoef, p_wnode + (size_t)l * MM * DD * DD, DD,
              (long long)DD * DD, 0, p_node, nullptr, nullptr, 0,
              NTOT, DD, MM * DD, DD, DD, 1);
        combine_kernel<<<NTOT, DD>>>(p_s, p_cnt, ln_w + (size_t)l * DD, ln_b + (size_t)l * DD,
                                     h_bias + (size_t)l * DD, p_node, p_trans,
                                     p_feat, l == 0 ? p_e1 : p_e2);
    }
    final_kernel<<<NTOT, DD>>>(embedding, p_e1, p_e2, fln_w, fln_b, out);
    (void)in_sizes; (void)n_in; (void)out_size;
}

// round 4
// speedup vs baseline: 2.7950x; 1.0897x over previous
#include <cuda_runtime.h>
#include <math.h>

#define N_USER 20000
#define N_ITEM 20000
#define NTOT   40000
#define DD     128
#define HH     4
#define HD     512     // H*D
#define MM     8
#define TT     5
#define E_UI_  40000
#define E_T_   16000

// ---------------- scratch (device globals; no allocation allowed) ----------
__device__ float    g_fc[(size_t)NTOT * HD];
__device__ float    g_rst[(size_t)N_USER * HD];
__device__ float    g_el[NTOT * HH];
__device__ float    g_er[NTOT * HH];
__device__ float    g_e[E_UI_ * HH];
__device__ unsigned g_emax[N_USER * HH];
__device__ float    g_denom[N_USER * HH];
__device__ float    g_trans[(size_t)NTOT * DD];
__device__ float    g_coef[(size_t)TT * E_T_ * MM];
__device__ float    g_ncoef[(size_t)NTOT * MM];
__device__ float    g_s[(size_t)NTOT * DD];
__device__ float    g_cnt[NTOT];
__device__ float    g_node[(size_t)NTOT * DD];
__device__ float    g_feat[(size_t)NTOT * DD];
__device__ float    g_emb1[(size_t)NTOT * DD];
__device__ float    g_emb2[(size_t)NTOT * DD];
// tf32-pre-rounded weights
__device__ float    g_wfc[2 * 2 * HD * DD];
__device__ float    g_wproj[2 * 2 * DD * HD];
__device__ float    g_wrel[2 * TT * MM * DD * DD];
__device__ float    g_wnode[2 * MM * DD * DD];

// ---------------- helpers ---------------------------------------------------
__device__ __forceinline__ float lrelu(float x) { return x > 0.f ? x : 0.2f * x; }
__device__ __forceinline__ float eluf(float x)  { return x > 0.f ? x : expm1f(x); }
__device__ __forceinline__ unsigned fordu(float f) {
    unsigned u = __float_as_uint(f);
    return (u & 0x80000000u) ? ~u : (u | 0x80000000u);
}
__device__ __forceinline__ float fordinv(unsigned u) {
    return __uint_as_float((u & 0x80000000u) ? (u & 0x7fffffffu) : ~u);
}
__device__ __forceinline__ unsigned f2tf32(float x) {
    unsigned r; asm("cvt.rna.tf32.f32 %0, %1;" : "=r"(r) : "f"(x)); return r;
}
__device__ __forceinline__ void mma1688(float* c, const unsigned* a, const unsigned* b) {
    asm volatile("mma.sync.aligned.m16n8k8.row.col.f32.tf32.tf32.f32 "
                 "{%0,%1,%2,%3},{%4,%5,%6,%7},{%8,%9},{%0,%1,%2,%3};"
                 : "+f"(c[0]), "+f"(c[1]), "+f"(c[2]), "+f"(c[3])
                 : "r"(a[0]), "r"(a[1]), "r"(a[2]), "r"(a[3]), "r"(b[0]), "r"(b[1]));
}
__device__ __forceinline__ void redv2(float* p, float a, float b) {
    asm volatile("red.global.add.v2.f32 [%0], {%1,%2};" :: "l"(p), "f"(a), "f"(b) : "memory");
}
__device__ __forceinline__ void redv4(float* p, float a, float b, float c, float d) {
    asm volatile("red.global.add.v4.f32 [%0], {%1,%2,%3,%4};"
                 :: "l"(p), "f"(a), "f"(b), "f"(c), "f"(d) : "memory");
}

__device__ __forceinline__ float blocksum128(float v, float* red) {
#pragma unroll
    for (int o = 16; o; o >>= 1) v += __shfl_down_sync(0xffffffffu, v, o);
    int lane = threadIdx.x & 31, w = threadIdx.x >> 5;
    if (lane == 0) red[w] = v;
    __syncthreads();
    float r = red[0] + red[1] + red[2] + red[3];
    __syncthreads();
    return r;
}

// ---------------- weight pre-round to tf32 (merged) -------------------------
__global__ void round_all(const float* i0, float* o0, int n0,
                          const float* i1, float* o1, int n1,
                          const float* i2, float* o2, int n2,
                          const float* i3, float* o3, int n3)
{
    int stride = gridDim.x * blockDim.x;
    for (int i = blockIdx.x * blockDim.x + threadIdx.x; i < n0; i += stride)
        o0[i] = __uint_as_float(f2tf32(i0[i]));
    for (int i = blockIdx.x * blockDim.x + threadIdx.x; i < n1; i += stride)
        o1[i] = __uint_as_float(f2tf32(i1[i]));
    for (int i = blockIdx.x * blockDim.x + threadIdx.x; i < n2; i += stride)
        o2[i] = __uint_as_float(f2tf32(i2[i]));
    for (int i = blockIdx.x * blockDim.x + threadIdx.x; i < n3; i += stride)
        o3[i] = __uint_as_float(f2tf32(i3[i]));
}

// ---------------- tf32 tensor-core GEMM -------------------------------------
// C[r,c] = sum_k A'[r,k] * B'[c,k]
// A'[r,k] = (coef ? coef[(t*Mrows+r)*8 + k/aSeg] : 1) * A[(gidx?gidx[t*Mrows+r]:r)*aSeg + k%aSeg]
// B'[c,k] = B[t*bTStride + (k/bSeg)*bStride + c*bSeg + k%bSeg]
// epilogue: scatter red.v2 via sidx, or store with bias+elu; optional fused
// attention reduction (el/er) when attnAl != nullptr (fc GEMM: col-tile == head).
#define BK 32
#define SMF 19456
#define SMB (SMF * 4)

__global__ __launch_bounds__(256, 2)
void gemm_tf32(const float* __restrict__ A, const int* __restrict__ gidx,
               const float* __restrict__ coef,
               const float* __restrict__ B, int bSeg, long long bStride, long long bTStride,
               float* __restrict__ C, const int* __restrict__ sidx,
               const float* __restrict__ bias, int act,
               const float* __restrict__ attnAl, const float* __restrict__ attnAr,
               float* __restrict__ elOut, float* __restrict__ erOut,
               int Mrows, int K, int aSeg, int ldc, int tilesPerT)
{
    extern __shared__ float sm[];
    float* sCoef = sm + 18432;
    float* sEl   = sm + 18432;       // reused: coef mode and attn mode are exclusive
    float* sEr   = sm + 18432 + 128;

    const int tid  = threadIdx.x;
    const int lane = tid & 31, wid = tid >> 5;
    const int warpM = wid & 3, warpN = wid >> 2;   // 4 x 2 warps; warp tile 32x64
    const int t    = blockIdx.y / tilesPerT;
    const int row0 = (blockIdx.y % tilesPerT) * 128;
    const int col0 = blockIdx.x * 128;

    const int lrow = tid >> 1;
    const int lcol = (tid & 1) * 16;
    const int growL  = row0 + lrow;
    const bool rowokL = growL < Mrows;
    const int arowL  = rowokL ? (gidx ? gidx[(long long)t * Mrows + growL] : growL) : 0;
    const float* AbaseL = A + (long long)arowL * aSeg + lcol;
    const float* BbaseL = B + t * bTStride + (long long)(col0 + lrow) * bSeg + lcol;
    const int aBytes = rowokL ? 16 : 0;

    if (coef) {
        for (int i = tid; i < 1024; i += 256) {
            int r = i >> 3, m = i & 7;
            int gr = row0 + r;
            sCoef[i] = (gr < Mrows) ? coef[((long long)t * Mrows + gr) * 8 + m] : 0.f;
        }
    }

    float acc[2][8][4];
#pragma unroll
    for (int i = 0; i < 2; i++)
#pragma unroll
        for (int j = 0; j < 8; j++)
#pragma unroll
            for (int q = 0; q < 4; q++) acc[i][j][q] = 0.f;

    const int ntiles = K / BK;

    auto loadTile = [&](int kt, int b) {
        const float* ga = AbaseL + (kt * BK) % aSeg;
        const float* gb = BbaseL + (long long)((kt * BK) / bSeg) * bStride + (kt * BK) % bSeg;
        unsigned da = (unsigned)__cvta_generic_to_shared(&sm[b * 9216 + lrow * 36 + lcol]);
        unsigned db = (unsigned)__cvta_generic_to_shared(&sm[b * 9216 + 4608 + lrow * 36 + lcol]);
#pragma unroll
        for (int j = 0; j < 4; j++) {
            asm volatile("cp.async.ca.shared.global [%0], [%1], 16, %2;"
                         :: "r"(da + j * 16), "l"(ga + j * 4), "r"(aBytes));
            asm volatile("cp.async.ca.shared.global [%0], [%1], 16;"
                         :: "r"(db + j * 16), "l"(gb + j * 4));
        }
    };

    loadTile(0, 0);
    asm volatile("cp.async.commit_group;");
    int buf = 0;
    for (int kt = 0; kt < ntiles; kt++) {
        if (kt + 1 < ntiles) {
            loadTile(kt + 1, buf ^ 1);
            asm volatile("cp.async.commit_group;");
            asm volatile("cp.async.wait_group 1;");
        } else {
            asm volatile("cp.async.wait_group 0;");
        }
        __syncthreads();

        const float* pA = sm + buf * 9216;
        const float* pB = pA + 4608;
        float cf[2][2];
        if (coef) {
            int seg = (kt * BK) / aSeg;
#pragma unroll
            for (int mt = 0; mt < 2; mt++) {
                int rr = warpM * 32 + mt * 16 + (lane >> 2);
                cf[mt][0] = sCoef[rr * 8 + seg];
                cf[mt][1] = sCoef[(rr + 8) * 8 + seg];
            }
        }
#pragma unroll
        for (int kk = 0; kk < BK; kk += 8) {
            unsigned af[2][4], bf[8][2];
#pragma unroll
            for (int mt = 0; mt < 2; mt++) {
                int rr = warpM * 32 + mt * 16 + (lane >> 2);
                int kc = kk + (lane & 3);
                float x0 = pA[rr * 36 + kc];
                float x1 = pA[(rr + 8) * 36 + kc];
                float x2 = pA[rr * 36 + kc + 4];
                float x3 = pA[(rr + 8) * 36 + kc + 4];
                if (coef) {
                    x0 *= cf[mt][0]; x1 *= cf[mt][1];
                    x2 *= cf[mt][0]; x3 *= cf[mt][1];
                }
                af[mt][0] = f2tf32(x0); af[mt][1] = f2tf32(x1);
                af[mt][2] = f2tf32(x2); af[mt][3] = f2tf32(x3);
            }
#pragma unroll
            for (int nt = 0; nt < 8; nt++) {
                int nn = warpN * 64 + nt * 8 + (lane >> 2);
                int kc = kk + (lane & 3);
                bf[nt][0] = __float_as_uint(pB[nn * 36 + kc]);
                bf[nt][1] = __float_as_uint(pB[nn * 36 + kc + 4]);
            }
#pragma unroll
            for (int mt = 0; mt < 2; mt++)
#pragma unroll
                for (int nt = 0; nt < 8; nt++)
                    mma1688(acc[mt][nt], af[mt], bf[nt]);
        }
        __syncthreads();
        buf ^= 1;
    }

    // epilogue
#pragma unroll
    for (int mt = 0; mt < 2; mt++)
#pragma unroll
        for (int h = 0; h < 2; h++) {
            int r = row0 + warpM * 32 + mt * 16 + (lane >> 2) + 8 * h;
            if (r >= Mrows) continue;
            if (sidx) {
                long long orow = sidx[(long long)t * Mrows + r];
                long long base = orow * ldc + col0;
#pragma unroll
                for (int nt = 0; nt < 8; nt++) {
                    int c = warpN * 64 + nt * 8 + 2 * (lane & 3);
                    redv2(&C[base + c], acc[mt][nt][2 * h], acc[mt][nt][2 * h + 1]);
                }
            } else {
                long long base = (long long)r * ldc + col0;
#pragma unroll
                for (int nt = 0; nt < 8; nt++) {
                    int c = warpN * 64 + nt * 8 + 2 * (lane & 3);
                    float v0 = acc[mt][nt][2 * h];
                    float v1 = acc[mt][nt][2 * h + 1];
                    if (bias) { v0 += bias[col0 + c]; v1 += bias[col0 + c + 1]; }
                    if (act == 1) { v0 = eluf(v0); v1 = eluf(v1); }
                    float2 v = make_float2(v0, v1);
                    *(float2*)&C[base + c] = v;
                }
            }
        }

    // fused attention score reduction (fc GEMM only: one head per col-tile)
    if (attnAl) {
        const int head = col0 >> 7;
        const float* alh = attnAl + head * DD;
        const float* arh = attnAr + head * DD;
        for (int i = tid; i < 128; i += 256) { sEl[i] = 0.f; sEr[i] = 0.f; }
        __syncthreads();
        float alv[16], arv[16];
#pragma unroll
        for (int nt = 0; nt < 8; nt++) {
            int c = warpN * 64 + nt * 8 + 2 * (lane & 3);
            alv[2 * nt]     = alh[c];     alv[2 * nt + 1] = alh[c + 1];
            arv[2 * nt]     = arh[c];     arv[2 * nt + 1] = arh[c + 1];
        }
#pragma unroll
        for (int mt = 0; mt < 2; mt++)
#pragma unroll
            for (int h = 0; h < 2; h++) {
                float pl = 0.f, pr = 0.f;
#pragma unroll
                for (int nt = 0; nt < 8; nt++) {
                    pl += acc[mt][nt][2 * h] * alv[2 * nt]
                        + acc[mt][nt][2 * h + 1] * alv[2 * nt + 1];
                    pr += acc[mt][nt][2 * h] * arv[2 * nt]
                        + acc[mt][nt][2 * h + 1] * arv[2 * nt + 1];
                }
                pl += __shfl_xor_sync(0xffffffffu, pl, 1);
                pl += __shfl_xor_sync(0xffffffffu, pl, 2);
                pr += __shfl_xor_sync(0xffffffffu, pr, 1);
                pr += __shfl_xor_sync(0xffffffffu, pr, 2);
                if ((lane & 3) == 0) {
                    int rl = warpM * 32 + mt * 16 + 8 * h + (lane >> 2);
                    atomicAdd(&sEl[rl], pl);
                    atomicAdd(&sEr[rl], pr);
                }
            }
        __syncthreads();
        if (tid < 128) {
            int r = row0 + tid;
            if (r < Mrows) {
                elOut[r * HH + head] = sEl[tid];
                erOut[r * HH + head] = sEr[tid];
            }
        }
    }
}

// ---------------- GAT edge passes -------------------------------------------
__global__ void edge_p1(const int* __restrict__ srcIdx, const int* __restrict__ dstIdx,
                        int srcOff, int dstOff,
                        const float* __restrict__ el, const float* __restrict__ er,
                        float* __restrict__ eBuf, unsigned* __restrict__ emax)
{
    int i = blockIdx.x * blockDim.x + threadIdx.x;
    if (i >= E_UI_ * HH) return;
    int e = i >> 2, h = i & 3;
    int s = srcIdx[e], dd = dstIdx[e];
    float v = lrelu(el[(s + srcOff) * HH + h] + er[(dd + dstOff) * HH + h]);
    eBuf[i] = v;
    atomicMax(&emax[dd * HH + h], fordu(v));
}

__global__ void edge_p2(const int* __restrict__ srcIdx, const int* __restrict__ dstIdx,
                        int srcOff,
                        const float* __restrict__ fc, const float* __restrict__ eBuf,
                        const unsigned* __restrict__ emax,
                        float* __restrict__ denom, float* __restrict__ rst)
{
    int w = (blockIdx.x * blockDim.x + threadIdx.x) >> 5;
    int lane = threadIdx.x & 31;
    if (w >= E_UI_ * HH) return;
    int e = w >> 2, h = w & 3;
    int s = srcIdx[e], dd = dstIdx[e];
    float ex = expf(eBuf[w] - fordinv(emax[dd * HH + h]));
    if (lane == 0) atomicAdd(&denom[dd * HH + h], ex);
    float4 v = ((const float4*)(fc + (long long)(s + srcOff) * HD + h * DD))[lane];
    float* dst = rst + (long long)dd * HD + h * DD + lane * 4;
    redv4(dst, ex * v.x, ex * v.y, ex * v.z, ex * v.w);
}

__global__ void gat_final(float* __restrict__ rst, const float* __restrict__ denom,
                          const float* __restrict__ bias, int nDst)
{
    long long i = (long long)blockIdx.x * blockDim.x + threadIdx.x;
    if (i >= (long long)nDst * HD) return;
    int c = (int)(i % HD);
    int n = (int)(i / HD);
    int h = c >> 7;
    float den = denom[n * HH + h];
    float v = den > 0.f ? rst[i] / den : 0.f;
    rst[i] = eluf(v + bias[c]);
}

// ---------------- memory layer coefficients ---------------------------------
__global__ void relcoef_kernel(const float* __restrict__ feat, const int* __restrict__ edge_dst,
                               const float* __restrict__ Wc, const float* __restrict__ bc,
                               float* __restrict__ coef)
{
    int warp = (blockIdx.x * blockDim.x + threadIdx.x) >> 5;
    int lane = threadIdx.x & 31;
    if (warp >= TT * E_T_) return;
    int t = warp / E_T_;
    int d = edge_dst[warp];
    float4 hv = ((const float4*)(feat + (long long)d * DD))[lane];
#pragma unroll
    for (int m = 0; m < MM; m++) {
        float4 w = ((const float4*)(Wc + ((long long)t * MM + m) * DD))[lane];
        float s = hv.x * w.x + hv.y * w.y + hv.z * w.z + hv.w * w.w;
#pragma unroll
        for (int o = 16; o; o >>= 1) s += __shfl_down_sync(0xffffffffu, s, o);
        if (lane == 0) coef[(long long)warp * MM + m] = lrelu(s + bc[t * MM + m]);
    }
}

__global__ void ncoef_kernel(const float* __restrict__ feat,
                             const float* __restrict__ Wc, const float* __restrict__ bc,
                             float* __restrict__ coef)
{
    int warp = (blockIdx.x * blockDim.x + threadIdx.x) >> 5;
    int lane = threadIdx.x & 31;
    if (warp >= NTOT) return;
    float4 hv = ((const float4*)(feat + (long long)warp * DD))[lane];
#pragma unroll
    for (int m = 0; m < MM; m++) {
        float4 w = ((const float4*)(Wc + (long long)m * DD))[lane];
        float s = hv.x * w.x + hv.y * w.y + hv.z * w.z + hv.w * w.w;
#pragma unroll
        for (int o = 16; o; o >>= 1) s += __shfl_down_sync(0xffffffffu, s, o);
        if (lane == 0) coef[(long long)warp * MM + m] = lrelu(s + bc[m]);
    }
}

__global__ void cnt_kernel(const int* __restrict__ edge_dst, float* __restrict__ cnt)
{
    int i = blockIdx.x * blockDim.x + threadIdx.x;
    if (i >= TT * E_T_) return;
    atomicAdd(&cnt[edge_dst[i]], 1.f);
}

// ---------------- memory-layer combine (LN + residuals) ---------------------
__global__ void combine_kernel(const float* __restrict__ s, const float* __restrict__ cnt,
                               const float* __restrict__ lnw, const float* __restrict__ lnb,
                               const float* __restrict__ hbias,
                               const float* __restrict__ node, const float* __restrict__ trans,
                               float* __restrict__ featOut, float* __restrict__ embOut)
{
    __shared__ float red[4];
    int n = blockIdx.x, d = threadIdx.x;
    float c = fmaxf(cnt[n], 1.f);
    float agg = s[(long long)n * DD + d] / c;
    float mean = blocksum128(agg, red) * (1.f / DD);
    float df = agg - mean;
    float var = blocksum128(df * df, red) * (1.f / DD);
    float rep = df * rsqrtf(var + 1e-5f) * lnw[d] + lnb[d] + hbias[d]
              + node[(long long)n * DD + d];
    float f = lrelu(rep) + trans[(long long)n * DD + d];
    featOut[(long long)n * DD + d] = f;
    embOut[(long long)n * DD + d]  = f;
}

// ---------------- final layernorm over concat(emb0, e1, e2) -----------------
__global__ void final_kernel(const float* __restrict__ emb0,
                             const float* __restrict__ e1, const float* __restrict__ e2,
                             const float* __restrict__ w, const float* __restrict__ b,
                             float* __restrict__ out)
{
    __shared__ float red[4];
    int n = blockIdx.x, d = threadIdx.x;
    float x0 = emb0[(long long)n * DD + d];
    float x1 = e1[(long long)n * DD + d];
    float x2 = e2[(long long)n * DD + d];
    float mean = blocksum128(x0 + x1 + x2, red) * (1.f / 384.f);
    float d0 = x0 - mean, d1 = x1 - mean, d2 = x2 - mean;
    float var = blocksum128(d0 * d0 + d1 * d1 + d2 * d2, red) * (1.f / 384.f);
    float rs = rsqrtf(var + 1e-5f);
    long long base = (long long)n * 384;
    out[base + d]       = d0 * rs * w[d]       + b[d];
    out[base + 128 + d] = d1 * rs * w[128 + d] + b[128 + d];
    out[base + 256 + d] = d2 * rs * w[256 + d] + b[256 + d];
}

// ---------------- host driver ------------------------------------------------
extern "C" void kernel_launch(void* const* d_in, const int* in_sizes, int n_in,
                              void* d_out, int out_size)
{
    const float* embedding = (const float*)d_in[0];
    const float* gat_fc_W  = (const float*)d_in[1];
    const float* gat_al    = (const float*)d_in[2];
    const float* gat_ar    = (const float*)d_in[3];
    const float* gat_bias  = (const float*)d_in[4];
    const float* proj_W    = (const float*)d_in[5];
    const float* proj_b    = (const float*)d_in[6];
    const float* rel_Wc    = (const float*)d_in[7];
    const float* rel_bc    = (const float*)d_in[8];
    const float* rel_Ww    = (const float*)d_in[9];
    const float* node_Wc   = (const float*)d_in[10];
    const float* node_bc   = (const float*)d_in[11];
    const float* node_Ww   = (const float*)d_in[12];
    const float* h_bias    = (const float*)d_in[13];
    const float* ln_w      = (const float*)d_in[14];
    const float* ln_b      = (const float*)d_in[15];
    const float* fln_w     = (const float*)d_in[16];
    const float* fln_b     = (const float*)d_in[17];
    const int*   src_u     = (const int*)d_in[18];
    const int*   dst_i     = (const int*)d_in[19];
    const int*   edge_src  = (const int*)d_in[20];
    const int*   edge_dst  = (const int*)d_in[21];
    float* out = (float*)d_out;

    float *p_fc, *p_rst, *p_el, *p_er, *p_e, *p_denom, *p_trans, *p_coef,
          *p_ncoef, *p_s, *p_cnt, *p_node, *p_feat, *p_e1, *p_e2,
          *p_wfc, *p_wproj, *p_wrel, *p_wnode;
    unsigned* p_emax;
    cudaGetSymbolAddress((void**)&p_fc, g_fc);
    cudaGetSymbolAddress((void**)&p_rst, g_rst);
    cudaGetSymbolAddress((void**)&p_el, g_el);
    cudaGetSymbolAddress((void**)&p_er, g_er);
    cudaGetSymbolAddress((void**)&p_e, g_e);
    cudaGetSymbolAddress((void**)&p_emax, g_emax);
    cudaGetSymbolAddress((void**)&p_denom, g_denom);
    cudaGetSymbolAddress((void**)&p_trans, g_trans);
    cudaGetSymbolAddress((void**)&p_coef, g_coef);
    cudaGetSymbolAddress((void**)&p_ncoef, g_ncoef);
    cudaGetSymbolAddress((void**)&p_s, g_s);
    cudaGetSymbolAddress((void**)&p_cnt, g_cnt);
    cudaGetSymbolAddress((void**)&p_node, g_node);
    cudaGetSymbolAddress((void**)&p_feat, g_feat);
    cudaGetSymbolAddress((void**)&p_e1, g_emb1);
    cudaGetSymbolAddress((void**)&p_e2, g_emb2);
    cudaGetSymbolAddress((void**)&p_wfc, g_wfc);
    cudaGetSymbolAddress((void**)&p_wproj, g_wproj);
    cudaGetSymbolAddress((void**)&p_wrel, g_wrel);
    cudaGetSymbolAddress((void**)&p_wnode, g_wnode);

    cudaFuncSetAttribute(gemm_tf32, cudaFuncAttributeMaxDynamicSharedMemorySize, SMB);

    auto gemmT = [&](const float* A, const int* gidx, const float* coefp,
                     const float* B, int bSeg, long long bStride, long long bTStride,
                     float* C, const int* sidx, const float* bias, int act,
                     const float* aAl, const float* aAr, float* elp, float* erp,
                     int M, int Nc, int K, int aSeg, int ldc, int tCount) {
        int tiles = (M + 127) / 128;
        dim3 g(Nc / 128, tiles * tCount);
        gemm_tf32<<<g, 256, SMB>>>(A, gidx, coefp, B, bSeg, bStride, bTStride,
                                   C, sidx, bias, act, aAl, aAr, elp, erp,
                                   M, K, aSeg, ldc, tiles);
    };

    round_all<<<512, 256>>>(gat_fc_W, p_wfc, 2*2*HD*DD,
                            proj_W, p_wproj, 2*2*DD*HD,
                            rel_Ww, p_wrel, 2*TT*MM*DD*DD,
                            node_Ww, p_wnode, 2*MM*DD*DD);

    cudaMemcpyAsync(p_feat, embedding, (size_t)NTOT * DD * 4, cudaMemcpyDeviceToDevice);
    cudaMemsetAsync(p_cnt, 0, NTOT * 4);
    cnt_kernel<<<(TT * E_T_ + 255) / 256, 256>>>(edge_dst, p_cnt);

    for (int l = 0; l < 2; l++) {
        for (int side = 0; side < 2; side++) {
            int g = l * 2 + side;
            gemmT(p_feat, nullptr, nullptr, p_wfc + (size_t)g * HD * DD, DD, 0, 0,
                  p_fc, nullptr, nullptr, 0,
                  gat_al + (size_t)g * HH * DD, gat_ar + (size_t)g * HH * DD, p_el, p_er,
                  NTOT, HD, DD, DD, HD, 1);
            cudaMemsetAsync(p_emax, 0, N_USER * HH * 4);
            cudaMemsetAsync(p_denom, 0, N_USER * HH * 4);
            cudaMemsetAsync(p_rst, 0, (size_t)N_USER * HD * 4);
            const int* sIdx = side == 0 ? dst_i : src_u;
            const int* dIdx = side == 0 ? src_u : dst_i;
            int sOff = side == 0 ? N_USER : 0;
            int dOff = side == 0 ? 0 : N_USER;
            edge_p1<<<(E_UI_ * HH + 255) / 256, 256>>>(sIdx, dIdx, sOff, dOff,
                                                       p_el, p_er, p_e, p_emax);
            edge_p2<<<(E_UI_ * HH * 32 + 255) / 256, 256>>>(sIdx, dIdx, sOff,
                                                            p_fc, p_e, p_emax, p_denom, p_rst);
            gat_final<<<((size_t)N_USER * HD + 255) / 256, 256>>>(
                p_rst, p_denom, gat_bias + (size_t)g * HD, N_USER);
            gemmT(p_rst, nullptr, nullptr, p_wproj + (size_t)g * DD * HD, HD, 0, 0,
                  p_trans + (size_t)side * N_USER * DD, nullptr,
                  proj_b + (size_t)g * DD, 1, nullptr, nullptr, nullptr, nullptr,
                  N_USER, DD, HD, HD, DD, 1);
        }
        // memory layer
        relcoef_kernel<<<(TT * E_T_ * 32 + 255) / 256, 256>>>(
            p_feat, edge_dst, rel_Wc + (size_t)l * TT * MM * DD,
            rel_bc + (size_t)l * TT * MM, p_coef);
        ncoef_kernel<<<(NTOT * 32 + 255) / 256, 256>>>(
            p_feat, node_Wc + (size_t)l * MM * DD, node_bc + (size_t)l * MM, p_ncoef);
        cudaMemsetAsync(p_s, 0, (size_t)NTOT * DD * 4);
        gemmT(p_feat, edge_src, p_coef,
              p_wrel + (size_t)l * TT * MM * DD * DD, DD, (long long)DD * DD,
              (long long)MM * DD * DD,
              p_s, edge_dst, nullptr, 0, nullptr, nullptr, nullptr, nullptr,
              E_T_, DD, MM * DD, DD, DD, TT);
        gemmT(p_feat, nullptr, p_ncoef, p_wnode + (size_t)l * MM * DD * DD, DD,
              (long long)DD * DD, 0, p_node, nullptr, nullptr, 0,
              nullptr, nullptr, nullptr, nullptr,
              NTOT, DD, MM * DD, DD, DD, 1);
        combine_kernel<<<NTOT, DD>>>(p_s, p_cnt, ln_w + (size_t)l * DD, ln_b + (size_t)l * DD,
                                     h_bias + (size_t)l * DD, p_node, p_trans,
                                     p_feat, l == 0 ? p_e1 : p_e2);
    }
    final_kernel<<<NTOT, DD>>>(embedding, p_e1, p_e2, fln_w, fln_b, out);
    (void)in_sizes; (void)n_in; (void)out_size;
}